// round 15
// baseline (speedup 1.0000x reference)
#include <cuda_runtime.h>

#define DDIM 4096
#define NTHREADS 512
#define GRID 148
#define R4 4      // rows per iteration
#define NBUF 3    // cp.async pipeline depth
#define WST 20    // wsum transposed row stride (floats); 80B keeps float4 aligned

// ---------------------------------------------------------------------------
// Compact-WY form of 8 sequential Householder reflections:
//   x_out = x - U d,  d = S c,  c = U^T x,  S = 2*(I+2L)^{-1}, U normalized.
//
// R10 schedule (best so far) + two micro-opts:
//  * wsum transposed (stride 20) so warp0's serial finish reads 4x LDS.128
//    instead of 16 scalar LDS;
//  * odd warps traverse rows in reverse order in dots/update to de-correlate
//    per-SMSP port contention across lockstep warps.
// u fully register-resident (64 regs/thread); x streams through a
// triple-buffered cp.async ring (private slots, wait_group 2) and is read
// from smem in both dot and update phases.
// smem: xbuf[3][4*4096] | wsum[32*20] | dsh2[64] | Ssh[64] | gsh[36] | rn[8]
// ---------------------------------------------------------------------------
extern __shared__ float smem[];

typedef unsigned long long u64;

__device__ __forceinline__ u64 ffma2(u64 a, u64 b, u64 c) {
    u64 d;
    asm("fma.rn.f32x2 %0, %1, %2, %3;" : "=l"(d) : "l"(a), "l"(b), "l"(c));
    return d;
}
__device__ __forceinline__ u64 pack2(float lo, float hi) {
    u64 d;
    asm("mov.b64 %0, {%1, %2};" : "=l"(d) : "f"(lo), "f"(hi));
    return d;
}
__device__ __forceinline__ void unpack2(u64 p, float& lo, float& hi) {
    asm("mov.b64 {%0, %1}, %2;" : "=f"(lo), "=f"(hi) : "l"(p));
}
__device__ __forceinline__ int tri_idx(int a, int b) {
    return a * (17 - a) / 2 + (b - a);  // packed upper-tri [36], a <= b
}

__global__ void __launch_bounds__(NTHREADS, 1)
hra_kernel(const float* __restrict__ X, const float* __restrict__ hra_u,
           float* __restrict__ Y, int nq) {
    float* xbuf = smem;                         // 3 * 4*4096
    float* wsum = xbuf + NBUF * R4 * DDIM;      // 32*20 (transposed, padded)
    float* dsh2 = wsum + 32 * WST;              // 64 (32 u64), 16B-aligned
    float* Ssh  = dsh2 + 64;                    // 64
    float* gsh  = Ssh + 64;                     // 36
    float* rn   = gsh + 36;                     // 8

    const int tid  = threadIdx.x;
    const int lane = tid & 31;
    const int warp = tid >> 5;

    // ---------------- Phase 0: Gram + S + per-thread u registers ----------
    if (tid < 36) gsh[tid] = 0.f;
    __syncthreads();
    {
        float acc[36];
#pragma unroll
        for (int t = 0; t < 36; t++) acc[t] = 0.f;
        for (int k = tid; k < DDIM; k += NTHREADS) {
            float4 a = reinterpret_cast<const float4*>(hra_u)[k * 2];
            float4 b = reinterpret_cast<const float4*>(hra_u)[k * 2 + 1];
            float v[8] = {a.x, a.y, a.z, a.w, b.x, b.y, b.z, b.w};
            int t = 0;
#pragma unroll
            for (int i = 0; i < 8; i++)
#pragma unroll
                for (int j = i; j < 8; j++)
                    acc[t++] += v[i] * v[j];
        }
#pragma unroll
        for (int t = 0; t < 36; t++) {
#pragma unroll
            for (int o = 16; o > 0; o >>= 1)
                acc[t] += __shfl_xor_sync(0xffffffffu, acc[t], o);
        }
        if (lane == 0)
            for (int t = 0; t < 36; t++) atomicAdd(&gsh[t], acc[t]);
    }
    __syncthreads();
    if (tid < 8) rn[tid] = rsqrtf(gsh[tri_idx(tid, tid)]);
    __syncthreads();
    if (tid < 8) {
        const int c = tid;  // column c of S: solve (I + 2L) x = 2 e_c
        float x[8];
#pragma unroll
        for (int i = 0; i < 8; i++) {
            float s = (i == c) ? 2.f : 0.f;
            for (int j = 0; j < i; j++) {
                float gji = gsh[tri_idx(j, i)] * rn[j] * rn[i];
                s -= 2.f * gji * x[j];
            }
            x[i] = s;
            Ssh[i * 8 + c] = x[i];
        }
    }
    __syncthreads();  // rn, Ssh ready

    // per-thread u registers: elements [4*tid, 4*tid+4) (chunk 0) and
    // [2048+4*tid, 2048+4*tid+4) (chunk 1) of each normalized vector.
    u64 up[8][4];
    {
        const float4* hu4 = reinterpret_cast<const float4*>(hra_u);
#pragma unroll
        for (int c = 0; c < 2; c++) {
            float uu[4][8];
#pragma unroll
            for (int e = 0; e < 4; e++) {
                int k = c * 2048 + 4 * tid + e;
                float4 t0 = hu4[k * 2 + 0];
                float4 t1 = hu4[k * 2 + 1];
                uu[e][0] = t0.x; uu[e][1] = t0.y; uu[e][2] = t0.z; uu[e][3] = t0.w;
                uu[e][4] = t1.x; uu[e][5] = t1.y; uu[e][6] = t1.z; uu[e][7] = t1.w;
            }
#pragma unroll
            for (int i = 0; i < 8; i++) {
                float r = rn[i];
                up[i][c * 2 + 0] = pack2(uu[0][i] * r, uu[1][i] * r);
                up[i][c * 2 + 1] = pack2(uu[2][i] * r, uu[3][i] * r);
            }
        }
    }

    // ---------------- Phase 1: main loop (4 rows / iteration) --------------
    const int t_self = (int)(__brev((unsigned)lane) >> 27);  // bitrev5(lane)
    const int rmask = (warp & 1) ? 3 : 0;  // odd warps reverse row order
    const unsigned xb_base = (unsigned)__cvta_generic_to_shared(xbuf);
    const unsigned BUF_BYTES = R4 * DDIM * 4u;

    int q = blockIdx.x;
    if (q >= nq) return;

    // prologue: prefetch q -> buf0, q+GRID -> buf1
#pragma unroll
    for (int pb = 0; pb < 2; pb++) {
        int qp = q + pb * GRID;
        int qc = qp < nq ? qp : q;
        const float4* xg = reinterpret_cast<const float4*>(X) + (size_t)qc * 4096;
#pragma unroll
        for (int r = 0; r < R4; r++) {
#pragma unroll
            for (int h = 0; h < 2; h++) {
                unsigned s = xb_base + pb * BUF_BYTES
                           + (unsigned)(r * 1024 + h * NTHREADS + tid) * 16u;
                const float4* g = xg + (r * 1024 + h * NTHREADS + tid);
                asm volatile("cp.async.cg.shared.global [%0], [%1], 16;"
                             :: "r"(s), "l"(g));
            }
        }
        asm volatile("cp.async.commit_group;");
    }

    int bcur = 0;
    for (; q < nq; q += GRID) {
        // prefetch q+2*GRID into buffer (bcur+2)%3
        {
            int bpf = bcur + 2; if (bpf >= NBUF) bpf -= NBUF;
            int qp = q + 2 * GRID;
            int qc = qp < nq ? qp : q;
            const float4* xg = reinterpret_cast<const float4*>(X) + (size_t)qc * 4096;
#pragma unroll
            for (int r = 0; r < R4; r++) {
#pragma unroll
                for (int h = 0; h < 2; h++) {
                    unsigned s = xb_base + bpf * BUF_BYTES
                               + (unsigned)(r * 1024 + h * NTHREADS + tid) * 16u;
                    const float4* g = xg + (r * 1024 + h * NTHREADS + tid);
                    asm volatile("cp.async.cg.shared.global [%0], [%1], 16;"
                                 :: "r"(s), "l"(g));
                }
            }
            asm volatile("cp.async.commit_group;");
        }
        asm volatile("cp.async.wait_group 2;");

        const ulonglong2* xb2 =
            reinterpret_cast<const ulonglong2*>(xbuf + bcur * (R4 * DDIM));

        // dots: val[rr*8+i] = <x_rr(thread chunks), u_i(thread chunks)>
        // (odd warps iterate rows in reverse to de-correlate port demand)
        float val[32];
#pragma unroll
        for (int r = 0; r < R4; r++) {
            const int rr = r ^ rmask;
            ulonglong2 xa = xb2[rr * 1024 + tid];            // chunk 0
            ulonglong2 xc = xb2[rr * 1024 + tid + NTHREADS]; // chunk 1
#pragma unroll
            for (int i = 0; i < 8; i++) {
                u64 a0 = ffma2(xa.x, up[i][0], 0ull);
                u64 a1 = ffma2(xa.y, up[i][1], 0ull);
                a0 = ffma2(xc.x, up[i][2], a0);
                a1 = ffma2(xc.y, up[i][3], a1);
                float l0, h0, l1, h1;
                unpack2(a0, l0, h0);
                unpack2(a1, l1, h1);
                val[rr * 8 + i] = (l0 + h0) + (l1 + h1);
            }
        }

        // 31-shfl multi-value butterfly; lane ends with sum of val[bitrev5(lane)]
#pragma unroll
        for (int s = 0; s < 5; s++) {
            const int m = 1 << s;
            const int h = 16 >> s;
#pragma unroll
            for (int k = 0; k < h; k++) {
                float send = (lane & m) ? val[k] : val[k + h];
                float rec  = __shfl_xor_sync(0xffffffffu, send, m);
                float keep = (lane & m) ? val[k + h] : val[k];
                val[k] = keep + rec;
            }
        }
        // transposed publish: wsum[value_index][warp]
        wsum[t_self * WST + warp] = val[0];
        __syncthreads();

        // warp 0: finish cross-warp reduction (4x LDS.128), apply S -> d,
        // publish negated duplicated f32x2 pairs
        if (warp == 0) {
            const float4* wrow =
                reinterpret_cast<const float4*>(wsum + lane * WST);
            float4 a = wrow[0], b = wrow[1], e = wrow[2], f = wrow[3];
            float c = ((a.x + a.y) + (a.z + a.w)) + ((b.x + b.y) + (b.z + b.w))
                    + ((e.x + e.y) + (e.z + e.w)) + ((f.x + f.y) + (f.z + f.w));
            const int i = lane & 7;
            float d = 0.f;
#pragma unroll
            for (int j = 0; j < 8; j++) {
                float cj = __shfl_sync(0xffffffffu, c, (lane & 24) + j);
                d += Ssh[i * 8 + j] * cj;
            }
            reinterpret_cast<u64*>(dsh2)[lane] = pack2(-d, -d);  // [row*8+i]
        }
        __syncthreads();

        // rank-8 update + streaming store (x re-read from smem)
        {
            const ulonglong2* dq = reinterpret_cast<const ulonglong2*>(dsh2);
            float4* y4 = reinterpret_cast<float4*>(Y) + (size_t)q * 4096;
#pragma unroll
            for (int r = 0; r < R4; r++) {
                const int rr = r ^ rmask;
                ulonglong2 p0 = dq[rr * 4 + 0];
                ulonglong2 p1 = dq[rr * 4 + 1];
                ulonglong2 p2 = dq[rr * 4 + 2];
                ulonglong2 p3 = dq[rr * 4 + 3];
                u64 nd[8] = {p0.x, p0.y, p1.x, p1.y, p2.x, p2.y, p3.x, p3.y};

                ulonglong2 xa = xb2[rr * 1024 + tid];
                ulonglong2 xc = xb2[rr * 1024 + tid + NTHREADS];
                u64 w0 = xa.x, w1 = xa.y, w2 = xc.x, w3 = xc.y;
#pragma unroll
                for (int i = 0; i < 8; i++) {
                    w0 = ffma2(nd[i], up[i][0], w0);
                    w1 = ffma2(nd[i], up[i][1], w1);
                    w2 = ffma2(nd[i], up[i][2], w2);
                    w3 = ffma2(nd[i], up[i][3], w3);
                }
                float4 o0, o1;
                unpack2(w0, o0.x, o0.y); unpack2(w1, o0.z, o0.w);
                unpack2(w2, o1.x, o1.y); unpack2(w3, o1.z, o1.w);
                __stcs(&y4[rr * 1024 + tid], o0);
                __stcs(&y4[rr * 1024 + tid + NTHREADS], o1);
            }
        }

        if (++bcur == NBUF) bcur = 0;
    }
}

extern "C" void kernel_launch(void* const* d_in, const int* in_sizes, int n_in,
                              void* d_out, int out_size) {
    const float* X = (const float*)d_in[0];      // (4, 2048, 4096) fp32
    const float* hra_u = (const float*)d_in[1];  // (4096, 8) fp32
    float* Y = (float*)d_out;

    const int nrows = in_sizes[0] / DDIM;        // 8192
    const int nq = nrows / R4;                   // 2048

    const size_t smem_bytes =
        (NBUF * R4 * DDIM + 32 * WST + 64 + 64 + 36 + 8) * sizeof(float);
    cudaFuncSetAttribute(hra_kernel,
                         cudaFuncAttributeMaxDynamicSharedMemorySize,
                         (int)smem_bytes);

    hra_kernel<<<GRID, NTHREADS, smem_bytes>>>(X, hra_u, Y, nq);
}

// round 16
// speedup vs baseline: 1.2254x; 1.2254x over previous
#include <cuda_runtime.h>

#define DDIM 4096
#define NTHREADS 512
#define GRID 148
#define R4 4      // rows per iteration
#define NBUF 3    // cp.async pipeline depth
#define WST 20    // wsum transposed row stride (floats); 80B keeps float4 aligned

// ---------------------------------------------------------------------------
// Compact-WY form of 8 sequential Householder reflections:
//   x_out = x - U d,  d = S c,  c = U^T x,  S = 2*(I+2L)^{-1}, U normalized.
//
// R10 schedule (best: 57.9us) + ONE micro-opt: wsum stored transposed
// ([value][warp], stride 20) so warp0's serial finish reads 4x LDS.128
// (conflict-free) + tree add instead of 16 dependent scalar LDS.
// u fully register-resident (64 regs/thread, zero u smem traffic); x streams
// through a triple-buffered cp.async ring (per-thread private slots,
// wait_group 2) and is read from smem in both dot and update phases.
// smem: xbuf[3][4*4096] | wsum[32*20] | dsh2[64] | Ssh[64] | gsh[36] | rn[8]
// ---------------------------------------------------------------------------
extern __shared__ float smem[];

typedef unsigned long long u64;

__device__ __forceinline__ u64 ffma2(u64 a, u64 b, u64 c) {
    u64 d;
    asm("fma.rn.f32x2 %0, %1, %2, %3;" : "=l"(d) : "l"(a), "l"(b), "l"(c));
    return d;
}
__device__ __forceinline__ u64 pack2(float lo, float hi) {
    u64 d;
    asm("mov.b64 %0, {%1, %2};" : "=l"(d) : "f"(lo), "f"(hi));
    return d;
}
__device__ __forceinline__ void unpack2(u64 p, float& lo, float& hi) {
    asm("mov.b64 {%0, %1}, %2;" : "=f"(lo), "=f"(hi) : "l"(p));
}
__device__ __forceinline__ int tri_idx(int a, int b) {
    return a * (17 - a) / 2 + (b - a);  // packed upper-tri [36], a <= b
}

__global__ void __launch_bounds__(NTHREADS, 1)
hra_kernel(const float* __restrict__ X, const float* __restrict__ hra_u,
           float* __restrict__ Y, int nq) {
    float* xbuf = smem;                         // 3 * 4*4096
    float* wsum = xbuf + NBUF * R4 * DDIM;      // 32*20 (transposed, padded)
    float* dsh2 = wsum + 32 * WST;              // 64 (32 u64), 16B-aligned
    float* Ssh  = dsh2 + 64;                    // 64
    float* gsh  = Ssh + 64;                     // 36
    float* rn   = gsh + 36;                     // 8

    const int tid  = threadIdx.x;
    const int lane = tid & 31;
    const int warp = tid >> 5;

    // ---------------- Phase 0: Gram + S + per-thread u registers ----------
    if (tid < 36) gsh[tid] = 0.f;
    __syncthreads();
    {
        float acc[36];
#pragma unroll
        for (int t = 0; t < 36; t++) acc[t] = 0.f;
        for (int k = tid; k < DDIM; k += NTHREADS) {
            float4 a = reinterpret_cast<const float4*>(hra_u)[k * 2];
            float4 b = reinterpret_cast<const float4*>(hra_u)[k * 2 + 1];
            float v[8] = {a.x, a.y, a.z, a.w, b.x, b.y, b.z, b.w};
            int t = 0;
#pragma unroll
            for (int i = 0; i < 8; i++)
#pragma unroll
            for (int j = i; j < 8; j++)
                    acc[t++] += v[i] * v[j];
        }
#pragma unroll
        for (int t = 0; t < 36; t++) {
#pragma unroll
            for (int o = 16; o > 0; o >>= 1)
                acc[t] += __shfl_xor_sync(0xffffffffu, acc[t], o);
        }
        if (lane == 0)
            for (int t = 0; t < 36; t++) atomicAdd(&gsh[t], acc[t]);
    }
    __syncthreads();
    if (tid < 8) rn[tid] = rsqrtf(gsh[tri_idx(tid, tid)]);
    __syncthreads();
    if (tid < 8) {
        const int c = tid;  // column c of S: solve (I + 2L) x = 2 e_c
        float x[8];
#pragma unroll
        for (int i = 0; i < 8; i++) {
            float s = (i == c) ? 2.f : 0.f;
            for (int j = 0; j < i; j++) {
                float gji = gsh[tri_idx(j, i)] * rn[j] * rn[i];
                s -= 2.f * gji * x[j];
            }
            x[i] = s;
            Ssh[i * 8 + c] = x[i];
        }
    }
    __syncthreads();  // rn, Ssh ready

    // per-thread u registers: elements [4*tid, 4*tid+4) (chunk 0) and
    // [2048+4*tid, 2048+4*tid+4) (chunk 1) of each normalized vector.
    u64 up[8][4];
    {
        const float4* hu4 = reinterpret_cast<const float4*>(hra_u);
#pragma unroll
        for (int c = 0; c < 2; c++) {
            float uu[4][8];
#pragma unroll
            for (int e = 0; e < 4; e++) {
                int k = c * 2048 + 4 * tid + e;
                float4 t0 = hu4[k * 2 + 0];
                float4 t1 = hu4[k * 2 + 1];
                uu[e][0] = t0.x; uu[e][1] = t0.y; uu[e][2] = t0.z; uu[e][3] = t0.w;
                uu[e][4] = t1.x; uu[e][5] = t1.y; uu[e][6] = t1.z; uu[e][7] = t1.w;
            }
#pragma unroll
            for (int i = 0; i < 8; i++) {
                float r = rn[i];
                up[i][c * 2 + 0] = pack2(uu[0][i] * r, uu[1][i] * r);
                up[i][c * 2 + 1] = pack2(uu[2][i] * r, uu[3][i] * r);
            }
        }
    }

    // ---------------- Phase 1: main loop (4 rows / iteration) --------------
    const int t_self = (int)(__brev((unsigned)lane) >> 27);  // bitrev5(lane)
    const unsigned xb_base = (unsigned)__cvta_generic_to_shared(xbuf);
    const unsigned BUF_BYTES = R4 * DDIM * 4u;

    int q = blockIdx.x;
    if (q >= nq) return;

    // prologue: prefetch q -> buf0, q+GRID -> buf1
#pragma unroll
    for (int pb = 0; pb < 2; pb++) {
        int qp = q + pb * GRID;
        int qc = qp < nq ? qp : q;
        const float4* xg = reinterpret_cast<const float4*>(X) + (size_t)qc * 4096;
#pragma unroll
        for (int r = 0; r < R4; r++) {
#pragma unroll
            for (int h = 0; h < 2; h++) {
                unsigned s = xb_base + pb * BUF_BYTES
                           + (unsigned)(r * 1024 + h * NTHREADS + tid) * 16u;
                const float4* g = xg + (r * 1024 + h * NTHREADS + tid);
                asm volatile("cp.async.cg.shared.global [%0], [%1], 16;"
                             :: "r"(s), "l"(g));
            }
        }
        asm volatile("cp.async.commit_group;");
    }

    int bcur = 0;
    for (; q < nq; q += GRID) {
        // prefetch q+2*GRID into buffer (bcur+2)%3
        {
            int bpf = bcur + 2; if (bpf >= NBUF) bpf -= NBUF;
            int qp = q + 2 * GRID;
            int qc = qp < nq ? qp : q;
            const float4* xg = reinterpret_cast<const float4*>(X) + (size_t)qc * 4096;
#pragma unroll
            for (int r = 0; r < R4; r++) {
#pragma unroll
                for (int h = 0; h < 2; h++) {
                    unsigned s = xb_base + bpf * BUF_BYTES
                               + (unsigned)(r * 1024 + h * NTHREADS + tid) * 16u;
                    const float4* g = xg + (r * 1024 + h * NTHREADS + tid);
                    asm volatile("cp.async.cg.shared.global [%0], [%1], 16;"
                                 :: "r"(s), "l"(g));
                }
            }
            asm volatile("cp.async.commit_group;");
        }
        asm volatile("cp.async.wait_group 2;");

        const ulonglong2* xb2 =
            reinterpret_cast<const ulonglong2*>(xbuf + bcur * (R4 * DDIM));

        // dots: val[r*8+i] = <x_r(thread chunks), u_i(thread chunks)>
        float val[32];
#pragma unroll
        for (int r = 0; r < R4; r++) {
            ulonglong2 xa = xb2[r * 1024 + tid];            // chunk 0
            ulonglong2 xc = xb2[r * 1024 + tid + NTHREADS]; // chunk 1
#pragma unroll
            for (int i = 0; i < 8; i++) {
                u64 a0 = ffma2(xa.x, up[i][0], 0ull);
                u64 a1 = ffma2(xa.y, up[i][1], 0ull);
                a0 = ffma2(xc.x, up[i][2], a0);
                a1 = ffma2(xc.y, up[i][3], a1);
                float l0, h0, l1, h1;
                unpack2(a0, l0, h0);
                unpack2(a1, l1, h1);
                val[r * 8 + i] = (l0 + h0) + (l1 + h1);
            }
        }

        // 31-shfl multi-value butterfly; lane ends with sum of val[bitrev5(lane)]
#pragma unroll
        for (int s = 0; s < 5; s++) {
            const int m = 1 << s;
            const int h = 16 >> s;
#pragma unroll
            for (int k = 0; k < h; k++) {
                float send = (lane & m) ? val[k] : val[k + h];
                float rec  = __shfl_xor_sync(0xffffffffu, send, m);
                float keep = (lane & m) ? val[k + h] : val[k];
                val[k] = keep + rec;
            }
        }
        // transposed publish: wsum[value_index][warp] (4-way bank conflict
        // on this single STS, negligible)
        wsum[t_self * WST + warp] = val[0];
        __syncthreads();

        // warp 0: finish via 4x LDS.128 (conflict-free) + tree add,
        // apply S -> d, publish negated duplicated f32x2 pairs
        if (warp == 0) {
            const float4* wrow =
                reinterpret_cast<const float4*>(wsum + lane * WST);
            float4 a = wrow[0], b = wrow[1], e = wrow[2], f = wrow[3];
            float c = (((a.x + a.y) + (a.z + a.w)) + ((b.x + b.y) + (b.z + b.w)))
                    + (((e.x + e.y) + (e.z + e.w)) + ((f.x + f.y) + (f.z + f.w)));
            const int i = lane & 7;
            float d = 0.f;
#pragma unroll
            for (int j = 0; j < 8; j++) {
                float cj = __shfl_sync(0xffffffffu, c, (lane & 24) + j);
                d += Ssh[i * 8 + j] * cj;
            }
            reinterpret_cast<u64*>(dsh2)[lane] = pack2(-d, -d);  // [row*8+i]
        }
        __syncthreads();

        // rank-8 update + streaming store (x re-read from smem)
        {
            const ulonglong2* dq = reinterpret_cast<const ulonglong2*>(dsh2);
            float4* y4 = reinterpret_cast<float4*>(Y) + (size_t)q * 4096;
#pragma unroll
            for (int r = 0; r < R4; r++) {
                ulonglong2 p0 = dq[r * 4 + 0];
                ulonglong2 p1 = dq[r * 4 + 1];
                ulonglong2 p2 = dq[r * 4 + 2];
                ulonglong2 p3 = dq[r * 4 + 3];
                u64 nd[8] = {p0.x, p0.y, p1.x, p1.y, p2.x, p2.y, p3.x, p3.y};

                ulonglong2 xa = xb2[r * 1024 + tid];
                ulonglong2 xc = xb2[r * 1024 + tid + NTHREADS];
                u64 w0 = xa.x, w1 = xa.y, w2 = xc.x, w3 = xc.y;
#pragma unroll
                for (int i = 0; i < 8; i++) {
                    w0 = ffma2(nd[i], up[i][0], w0);
                    w1 = ffma2(nd[i], up[i][1], w1);
                    w2 = ffma2(nd[i], up[i][2], w2);
                    w3 = ffma2(nd[i], up[i][3], w3);
                }
                float4 o0, o1;
                unpack2(w0, o0.x, o0.y); unpack2(w1, o0.z, o0.w);
                unpack2(w2, o1.x, o1.y); unpack2(w3, o1.z, o1.w);
                __stcs(&y4[r * 1024 + tid], o0);
                __stcs(&y4[r * 1024 + tid + NTHREADS], o1);
            }
        }

        if (++bcur == NBUF) bcur = 0;
    }
}

extern "C" void kernel_launch(void* const* d_in, const int* in_sizes, int n_in,
                              void* d_out, int out_size) {
    const float* X = (const float*)d_in[0];      // (4, 2048, 4096) fp32
    const float* hra_u = (const float*)d_in[1];  // (4096, 8) fp32
    float* Y = (float*)d_out;

    const int nrows = in_sizes[0] / DDIM;        // 8192
    const int nq = nrows / R4;                   // 2048

    const size_t smem_bytes =
        (NBUF * R4 * DDIM + 32 * WST + 64 + 64 + 36 + 8) * sizeof(float);
    cudaFuncSetAttribute(hra_kernel,
                         cudaFuncAttributeMaxDynamicSharedMemorySize,
                         (int)smem_bytes);

    hra_kernel<<<GRID, NTHREADS, smem_bytes>>>(X, hra_u, Y, nq);
}

// round 17
// speedup vs baseline: 1.3520x; 1.1033x over previous
#include <cuda_runtime.h>

#define DDIM 4096
#define NTHREADS 512
#define GRID 148
#define R4 4      // rows per iteration
#define NBUF 3    // cp.async pipeline depth

// ---------------------------------------------------------------------------
// Compact-WY form of 8 sequential Householder reflections:
//   x_out = x - U d,  d = S c,  c = U^T x,  S = 2*(I+2L)^{-1}, U normalized.
//
// Exact R10 schedule (best measured: 57.9us) with ONE change: each
// iteration's prefetch is split into TWO commit groups issued ~2000 cycles
// apart (after dot-LDS and after bar1) to smooth per-SM DRAM demand.
// wait_group 2 at the loop top therefore means "2 newest GROUPS pending" =
// the two halves of buffer k+1... with 2 groups per iteration the two
// pending groups at the wait are exactly next iteration's buffer; the
// current buffer's groups (issued 2 iterations ago) are drained.
// u fully register-resident (64 regs/thread); x streams through a
// triple-buffered cp.async ring (per-thread private slots) and is read from
// smem in both dot and update phases.
// smem: xbuf[3][4*4096] | wsum[16*32] | dsh2[64] | Ssh[64] | gsh[36] | rn[8]
// ---------------------------------------------------------------------------
extern __shared__ float smem[];

typedef unsigned long long u64;

__device__ __forceinline__ u64 ffma2(u64 a, u64 b, u64 c) {
    u64 d;
    asm("fma.rn.f32x2 %0, %1, %2, %3;" : "=l"(d) : "l"(a), "l"(b), "l"(c));
    return d;
}
__device__ __forceinline__ u64 pack2(float lo, float hi) {
    u64 d;
    asm("mov.b64 %0, {%1, %2};" : "=l"(d) : "f"(lo), "f"(hi));
    return d;
}
__device__ __forceinline__ void unpack2(u64 p, float& lo, float& hi) {
    asm("mov.b64 {%0, %1}, %2;" : "=f"(lo), "=f"(hi) : "l"(p));
}
__device__ __forceinline__ int tri_idx(int a, int b) {
    return a * (17 - a) / 2 + (b - a);  // packed upper-tri [36], a <= b
}

__global__ void __launch_bounds__(NTHREADS, 1)
hra_kernel(const float* __restrict__ X, const float* __restrict__ hra_u,
           float* __restrict__ Y, int nq) {
    float* xbuf = smem;                         // 3 * 4*4096
    float* wsum = xbuf + NBUF * R4 * DDIM;      // 16*32
    float* dsh2 = wsum + 16 * 32;               // 64 (32 u64), 16B-aligned
    float* Ssh  = dsh2 + 64;                    // 64
    float* gsh  = Ssh + 64;                     // 36
    float* rn   = gsh + 36;                     // 8

    const int tid  = threadIdx.x;
    const int lane = tid & 31;
    const int warp = tid >> 5;

    // ---------------- Phase 0: Gram + S + per-thread u registers ----------
    if (tid < 36) gsh[tid] = 0.f;
    __syncthreads();
    {
        float acc[36];
#pragma unroll
        for (int t = 0; t < 36; t++) acc[t] = 0.f;
        for (int k = tid; k < DDIM; k += NTHREADS) {
            float4 a = reinterpret_cast<const float4*>(hra_u)[k * 2];
            float4 b = reinterpret_cast<const float4*>(hra_u)[k * 2 + 1];
            float v[8] = {a.x, a.y, a.z, a.w, b.x, b.y, b.z, b.w};
            int t = 0;
#pragma unroll
            for (int i = 0; i < 8; i++)
#pragma unroll
                for (int j = i; j < 8; j++)
                    acc[t++] += v[i] * v[j];
        }
#pragma unroll
        for (int t = 0; t < 36; t++) {
#pragma unroll
            for (int o = 16; o > 0; o >>= 1)
                acc[t] += __shfl_xor_sync(0xffffffffu, acc[t], o);
        }
        if (lane == 0)
            for (int t = 0; t < 36; t++) atomicAdd(&gsh[t], acc[t]);
    }
    __syncthreads();
    if (tid < 8) rn[tid] = rsqrtf(gsh[tri_idx(tid, tid)]);
    __syncthreads();
    if (tid < 8) {
        const int c = tid;  // column c of S: solve (I + 2L) x = 2 e_c
        float x[8];
#pragma unroll
        for (int i = 0; i < 8; i++) {
            float s = (i == c) ? 2.f : 0.f;
            for (int j = 0; j < i; j++) {
                float gji = gsh[tri_idx(j, i)] * rn[j] * rn[i];
                s -= 2.f * gji * x[j];
            }
            x[i] = s;
            Ssh[i * 8 + c] = x[i];
        }
    }
    __syncthreads();  // rn, Ssh ready

    // per-thread u registers: elements [4*tid, 4*tid+4) (chunk 0) and
    // [2048+4*tid, 2048+4*tid+4) (chunk 1) of each normalized vector.
    u64 up[8][4];
    {
        const float4* hu4 = reinterpret_cast<const float4*>(hra_u);
#pragma unroll
        for (int c = 0; c < 2; c++) {
            float uu[4][8];
#pragma unroll
            for (int e = 0; e < 4; e++) {
                int k = c * 2048 + 4 * tid + e;
                float4 t0 = hu4[k * 2 + 0];
                float4 t1 = hu4[k * 2 + 1];
                uu[e][0] = t0.x; uu[e][1] = t0.y; uu[e][2] = t0.z; uu[e][3] = t0.w;
                uu[e][4] = t1.x; uu[e][5] = t1.y; uu[e][6] = t1.z; uu[e][7] = t1.w;
            }
#pragma unroll
            for (int i = 0; i < 8; i++) {
                float r = rn[i];
                up[i][c * 2 + 0] = pack2(uu[0][i] * r, uu[1][i] * r);
                up[i][c * 2 + 1] = pack2(uu[2][i] * r, uu[3][i] * r);
            }
        }
    }

    // ---------------- Phase 1: main loop (4 rows / iteration) --------------
    const int t_self = (int)(__brev((unsigned)lane) >> 27);  // bitrev5(lane)
    const unsigned xb_base = (unsigned)__cvta_generic_to_shared(xbuf);
    const unsigned BUF_BYTES = R4 * DDIM * 4u;

    // issue cp.async for rows [r0, r0+2) of quad qq into buffer `buf`
#define PREFETCH_HALF(buf, qq, r0)                                            \
    do {                                                                      \
        const float4* xg = reinterpret_cast<const float4*>(X)                 \
                         + (size_t)(qq) * 4096;                               \
        _Pragma("unroll")                                                     \
        for (int r = (r0); r < (r0) + 2; r++) {                               \
            _Pragma("unroll")                                                 \
            for (int h = 0; h < 2; h++) {                                     \
                unsigned s = xb_base + (buf) * BUF_BYTES                      \
                           + (unsigned)(r * 1024 + h * NTHREADS + tid) * 16u; \
                const float4* g = xg + (r * 1024 + h * NTHREADS + tid);       \
                asm volatile("cp.async.cg.shared.global [%0], [%1], 16;"      \
                             :: "r"(s), "l"(g));                              \
            }                                                                 \
        }                                                                     \
        asm volatile("cp.async.commit_group;");                               \
    } while (0)

    int q = blockIdx.x;
    if (q >= nq) return;

    // prologue: q -> buf0 (2 groups), q+GRID -> buf1 (2 groups)
#pragma unroll
    for (int pb = 0; pb < 2; pb++) {
        int qp = q + pb * GRID;
        int qc = qp < nq ? qp : q;
        PREFETCH_HALF(pb, qc, 0);
        PREFETCH_HALF(pb, qc, 2);
    }

    int bcur = 0;
    for (; q < nq; q += GRID) {
        // drain everything except the 2 newest groups (= buffer k+1's two
        // halves) -> current buffer k is complete
        asm volatile("cp.async.wait_group 2;");

        const ulonglong2* xb2 =
            reinterpret_cast<const ulonglong2*>(xbuf + bcur * (R4 * DDIM));

        int bpf = bcur + 2; if (bpf >= NBUF) bpf -= NBUF;
        int qp = q + 2 * GRID;
        int qc = qp < nq ? qp : q;

        // dots: val[r*8+i] = <x_r(thread chunks), u_i(thread chunks)>
        float val[32];
#pragma unroll
        for (int r = 0; r < R4; r++) {
            ulonglong2 xa = xb2[r * 1024 + tid];            // chunk 0
            ulonglong2 xc = xb2[r * 1024 + tid + NTHREADS]; // chunk 1
#pragma unroll
            for (int i = 0; i < 8; i++) {
                u64 a0 = ffma2(xa.x, up[i][0], 0ull);
                u64 a1 = ffma2(xa.y, up[i][1], 0ull);
                a0 = ffma2(xc.x, up[i][2], a0);
                a1 = ffma2(xc.y, up[i][3], a1);
                float l0, h0, l1, h1;
                unpack2(a0, l0, h0);
                unpack2(a1, l1, h1);
                val[r * 8 + i] = (l0 + h0) + (l1 + h1);
            }
        }

        // first half of next-next buffer's prefetch (dot-LDS already issued)
        PREFETCH_HALF(bpf, qc, 0);

        // 31-shfl multi-value butterfly; lane ends with sum of val[bitrev5(lane)]
#pragma unroll
        for (int s = 0; s < 5; s++) {
            const int m = 1 << s;
            const int h = 16 >> s;
#pragma unroll
            for (int k = 0; k < h; k++) {
                float send = (lane & m) ? val[k] : val[k + h];
                float rec  = __shfl_xor_sync(0xffffffffu, send, m);
                float keep = (lane & m) ? val[k + h] : val[k];
                val[k] = keep + rec;
            }
        }
        wsum[warp * 32 + t_self] = val[0];
        __syncthreads();

        // second half of the prefetch (~2000 cycles after the first)
        PREFETCH_HALF(bpf, qc, 2);

        // warp 0: finish cross-warp reduction (c), apply S -> d,
        // publish negated duplicated f32x2 pairs
        if (warp == 0) {
            float c = 0.f;
#pragma unroll
            for (int w = 0; w < 16; w++) c += wsum[w * 32 + lane];
            const int i = lane & 7;
            float d = 0.f;
#pragma unroll
            for (int j = 0; j < 8; j++) {
                float cj = __shfl_sync(0xffffffffu, c, (lane & 24) + j);
                d += Ssh[i * 8 + j] * cj;
            }
            reinterpret_cast<u64*>(dsh2)[lane] = pack2(-d, -d);  // [row*8+i]
        }
        __syncthreads();

        // rank-8 update + streaming store (x re-read from smem)
        {
            const ulonglong2* dq = reinterpret_cast<const ulonglong2*>(dsh2);
            float4* y4 = reinterpret_cast<float4*>(Y) + (size_t)q * 4096;
#pragma unroll
            for (int r = 0; r < R4; r++) {
                ulonglong2 p0 = dq[r * 4 + 0];
                ulonglong2 p1 = dq[r * 4 + 1];
                ulonglong2 p2 = dq[r * 4 + 2];
                ulonglong2 p3 = dq[r * 4 + 3];
                u64 nd[8] = {p0.x, p0.y, p1.x, p1.y, p2.x, p2.y, p3.x, p3.y};

                ulonglong2 xa = xb2[r * 1024 + tid];
                ulonglong2 xc = xb2[r * 1024 + tid + NTHREADS];
                u64 w0 = xa.x, w1 = xa.y, w2 = xc.x, w3 = xc.y;
#pragma unroll
                for (int i = 0; i < 8; i++) {
                    w0 = ffma2(nd[i], up[i][0], w0);
                    w1 = ffma2(nd[i], up[i][1], w1);
                    w2 = ffma2(nd[i], up[i][2], w2);
                    w3 = ffma2(nd[i], up[i][3], w3);
                }
                float4 o0, o1;
                unpack2(w0, o0.x, o0.y); unpack2(w1, o0.z, o0.w);
                unpack2(w2, o1.x, o1.y); unpack2(w3, o1.z, o1.w);
                __stcs(&y4[r * 1024 + tid], o0);
                __stcs(&y4[r * 1024 + tid + NTHREADS], o1);
            }
        }

        if (++bcur == NBUF) bcur = 0;
    }
#undef PREFETCH_HALF
}

extern "C" void kernel_launch(void* const* d_in, const int* in_sizes, int n_in,
                              void* d_out, int out_size) {
    const float* X = (const float*)d_in[0];      // (4, 2048, 4096) fp32
    const float* hra_u = (const float*)d_in[1];  // (4096, 8) fp32
    float* Y = (float*)d_out;

    const int nrows = in_sizes[0] / DDIM;        // 8192
    const int nq = nrows / R4;                   // 2048

    const size_t smem_bytes =
        (NBUF * R4 * DDIM + 16 * 32 + 64 + 64 + 36 + 8) * sizeof(float);
    cudaFuncSetAttribute(hra_kernel,
                         cudaFuncAttributeMaxDynamicSharedMemorySize,
                         (int)smem_bytes);

    hra_kernel<<<GRID, NTHREADS, smem_bytes>>>(X, hra_u, Y, nq);
}